// round 4
// baseline (speedup 1.0000x reference)
#include <cuda_runtime.h>
#include <math.h>

#define P 4096
#define BM 128
#define BN 128
#define BK 8
#define TM 8
#define TN 8
#define NTHREADS 256

// Scratch (no allocations allowed -> __device__ globals)
__device__ float  g_Wm[(size_t)P * P];  // W_matrix (aligned; copied to out+1)
__device__ float  g_P[(size_t)P * P];   // primary = W_matrix @ target - source
__device__ float  g_W[P];               // row sums of W_beta
__device__ float  g_scale[P];           // W^2 / (s*W^2 + 1)
__device__ double g_s;                  // ||target||_F^2
__device__ double g_ss;                 // sum of squares of W_beta @ primary

// ---------------------------------------------------------------------------
__global__ void zero_kernel() {
    g_s = 0.0;
    g_ss = 0.0;
}

__global__ void sumsq_kernel(const float* __restrict__ X) {
    __shared__ float sdata[NTHREADS];
    float acc = 0.f;
    size_t n = (size_t)P * P;
    for (size_t i = (size_t)blockIdx.x * blockDim.x + threadIdx.x; i < n;
         i += (size_t)gridDim.x * blockDim.x) {
        float v = X[i];
        acc += v * v;
    }
    sdata[threadIdx.x] = acc;
    __syncthreads();
    for (int s = NTHREADS / 2; s > 0; s >>= 1) {
        if (threadIdx.x < s) sdata[threadIdx.x] += sdata[threadIdx.x + s];
        __syncthreads();
    }
    if (threadIdx.x == 0) atomicAdd(&g_s, (double)sdata[0]);
}

__global__ void rowsum_kernel(const float* __restrict__ Wb) {
    __shared__ float sdata[NTHREADS];
    int row = blockIdx.x;
    const float* rp = Wb + (size_t)row * P;
    float acc = 0.f;
    for (int j = threadIdx.x; j < P; j += NTHREADS) acc += rp[j];
    sdata[threadIdx.x] = acc;
    __syncthreads();
    for (int s = NTHREADS / 2; s > 0; s >>= 1) {
        if (threadIdx.x < s) sdata[threadIdx.x] += sdata[threadIdx.x + s];
        __syncthreads();
    }
    if (threadIdx.x == 0) g_W[row] = sdata[0];
}

__global__ void scale_kernel() {
    int i = blockIdx.x * blockDim.x + threadIdx.x;
    if (i < P) {
        float w  = g_W[i];
        float w2 = w * w;
        float s  = (float)g_s;
        g_scale[i] = w2 / (s * w2 + 1.0f);
    }
}

__global__ void final_kernel(float* __restrict__ out) {
    out[0] = (float)sqrt(g_ss);
}

// ---------------------------------------------------------------------------
// Tiled SGEMM, 128x128 block tile, 8x8 per thread, BK=8, 256 threads.
// EPI 0: g_Wm[i,j] = g_scale[i] * acc
// EPI 1: g_P[i,j]  = acc - D[i,j]                   (D = source)
// EPI 2: accumulate sum(acc^2) into g_ss            (nothing written per-elem)
// BT true:  B is [N,K] row-major -> C = A * B^T  (dot of rows)
// BT false: B is [K,N] row-major -> C = A * B
// A_GWM / B_GP: read operand from device scratch instead of param.
template <int EPI, bool BT, bool A_GWM, bool B_GP>
__global__ void __launch_bounds__(NTHREADS, 2)
gemm_kernel(const float* __restrict__ Aparam, const float* __restrict__ Bparam,
            const float* __restrict__ D) {
    __shared__ float As[BK][BM];
    __shared__ float Bs[BK][BN];

    const float* A = A_GWM ? g_Wm : Aparam;
    const float* B = B_GP ? g_P : Bparam;

    const int tid     = threadIdx.x;
    const int rowBase = blockIdx.y * BM;
    const int colBase = blockIdx.x * BN;

    // A tile loader: 128 rows x 8 cols, one float4 per thread, store transposed
    const int aRow = tid >> 1;
    const int aCol = (tid & 1) * 4;
    // B tile loader (NN): 8 rows x 128 cols, one float4 per thread
    const int bRowN = tid >> 5;
    const int bColN = (tid & 31) * 4;

    const int mBase = (tid >> 4) * TM;  // 0..120
    const int nBase = (tid & 15) * TN;  // 0..120

    float acc[TM][TN];
#pragma unroll
    for (int i = 0; i < TM; i++)
#pragma unroll
        for (int j = 0; j < TN; j++) acc[i][j] = 0.f;

    for (int k0 = 0; k0 < P; k0 += BK) {
        // load A tile (transposed into smem)
        float4 av = *(const float4*)(A + (size_t)(rowBase + aRow) * P + k0 + aCol);
        As[aCol + 0][aRow] = av.x;
        As[aCol + 1][aRow] = av.y;
        As[aCol + 2][aRow] = av.z;
        As[aCol + 3][aRow] = av.w;

        if (BT) {
            // B[j,k]: load rows of B like A, transpose into Bs[k][j]
            float4 bv = *(const float4*)(B + (size_t)(colBase + aRow) * P + k0 + aCol);
            Bs[aCol + 0][aRow] = bv.x;
            Bs[aCol + 1][aRow] = bv.y;
            Bs[aCol + 2][aRow] = bv.z;
            Bs[aCol + 3][aRow] = bv.w;
        } else {
            // B[k,j]: straight copy
            float4 bv = *(const float4*)(B + (size_t)(k0 + bRowN) * P + colBase + bColN);
            *(float4*)&Bs[bRowN][bColN] = bv;
        }
        __syncthreads();

#pragma unroll
        for (int k = 0; k < BK; k++) {
            float am[TM], bn[TN];
            *(float4*)&am[0] = *(const float4*)&As[k][mBase];
            *(float4*)&am[4] = *(const float4*)&As[k][mBase + 4];
            *(float4*)&bn[0] = *(const float4*)&Bs[k][nBase];
            *(float4*)&bn[4] = *(const float4*)&Bs[k][nBase + 4];
#pragma unroll
            for (int i = 0; i < TM; i++)
#pragma unroll
                for (int j = 0; j < TN; j++) acc[i][j] += am[i] * bn[j];
        }
        __syncthreads();
    }

    if (EPI == 0) {
#pragma unroll
        for (int i = 0; i < TM; i++) {
            int r = rowBase + mBase + i;
            float sc = g_scale[r];
            float4 v0, v1;
            v0.x = sc * acc[i][0]; v0.y = sc * acc[i][1];
            v0.z = sc * acc[i][2]; v0.w = sc * acc[i][3];
            v1.x = sc * acc[i][4]; v1.y = sc * acc[i][5];
            v1.z = sc * acc[i][6]; v1.w = sc * acc[i][7];
            *(float4*)(g_Wm + (size_t)r * P + colBase + nBase)     = v0;
            *(float4*)(g_Wm + (size_t)r * P + colBase + nBase + 4) = v1;
        }
    } else if (EPI == 1) {
#pragma unroll
        for (int i = 0; i < TM; i++) {
            int r = rowBase + mBase + i;
            const float* dp = D + (size_t)r * P + colBase + nBase;
            float4 d0 = *(const float4*)(dp);
            float4 d1 = *(const float4*)(dp + 4);
            float4 v0, v1;
            v0.x = acc[i][0] - d0.x; v0.y = acc[i][1] - d0.y;
            v0.z = acc[i][2] - d0.z; v0.w = acc[i][3] - d0.w;
            v1.x = acc[i][4] - d1.x; v1.y = acc[i][5] - d1.y;
            v1.z = acc[i][6] - d1.z; v1.w = acc[i][7] - d1.w;
            *(float4*)(g_P + (size_t)r * P + colBase + nBase)     = v0;
            *(float4*)(g_P + (size_t)r * P + colBase + nBase + 4) = v1;
        }
    } else {
        // EPI 2: sum of squares
        float local = 0.f;
#pragma unroll
        for (int i = 0; i < TM; i++)
#pragma unroll
            for (int j = 0; j < TN; j++) local += acc[i][j] * acc[i][j];
        __shared__ float sdata[NTHREADS];
        sdata[tid] = local;
        __syncthreads();
        for (int s = NTHREADS / 2; s > 0; s >>= 1) {
            if (tid < s) sdata[tid] += sdata[tid + s];
            __syncthreads();
        }
        if (tid == 0) atomicAdd(&g_ss, (double)sdata[0]);
    }
}

// ---------------------------------------------------------------------------
extern "C" void kernel_launch(void* const* d_in, const int* in_sizes, int n_in,
                              void* d_out, int out_size) {
    const float* target = (const float*)d_in[0];
    const float* source = (const float*)d_in[1];
    const float* Wbeta  = (const float*)d_in[2];
    float* out = (float*)d_out;
    // Output layout: out[0] = loss, out[1:] = W_matrix (row-major).
    // out+1 is only 4B-aligned -> never touched with vector accesses; the
    // aligned scratch g_Wm is the working copy, published via memcpyAsync.

    zero_kernel<<<1, 1>>>();
    sumsq_kernel<<<2048, NTHREADS>>>(target);
    rowsum_kernel<<<P, NTHREADS>>>(Wbeta);
    scale_kernel<<<P / NTHREADS, NTHREADS>>>();

    dim3 grid(P / BN, P / BM);
    // GEMM1: g_Wm = diag(scale) * (source @ target^T)
    gemm_kernel<0, true, false, false><<<grid, NTHREADS>>>(source, target, nullptr);

    // Publish W_matrix to the (unaligned) output slot. D2D async copy is
    // graph-capturable and allocation-free.
    void* wm_dev = nullptr;
    cudaGetSymbolAddress(&wm_dev, g_Wm);
    cudaMemcpyAsync(out + 1, wm_dev, (size_t)P * P * sizeof(float),
                    cudaMemcpyDeviceToDevice);

    // GEMM2: g_P = g_Wm @ target - source
    gemm_kernel<1, false, true, false><<<grid, NTHREADS>>>(nullptr, target, source);
    // GEMM3: g_ss = sum((W_beta @ g_P)^2)
    gemm_kernel<2, false, false, true><<<grid, NTHREADS>>>(Wbeta, nullptr, nullptr);

    final_kernel<<<1, 1>>>(out);
}

// round 6
// speedup vs baseline: 3.6773x; 3.6773x over previous
#include <cuda_runtime.h>
#include <cuda_bf16.h>
#include <cstdint>
#include <math.h>

#define P 4096
#define NTH 256
#define BM 128
#define BN 128
#define BKF 32                 // K elems per chunk
#define NCH (P / BKF)          // 128
#define LDT 40                 // padded smem row length (bf16 elems) = 80B
#define TILE_B (128 * LDT * 2) // 10240 bytes per operand tile

// ---------------------------------------------------------------- scratch
__device__ float  g_Wm[(size_t)P * P];
__device__ float  g_tgtT[(size_t)P * P];
__device__ float  g_srcT[(size_t)P * P];
__device__ float  g_PT[(size_t)P * P];
__device__ float  g_W[P];
__device__ float  g_scale[P];
__device__ double g_s;
__device__ double g_ss;

// ---------------------------------------------------------------- helpers
__device__ __forceinline__ uint32_t smem_to_u32(const void* p) {
    uint32_t a;
    asm("{ .reg .u64 t; cvta.to.shared.u64 t, %1; cvt.u32.u64 %0, t; }" : "=r"(a) : "l"(p));
    return a;
}
__device__ __forceinline__ void ldsm4(uint32_t* r, uint32_t addr) {
    asm volatile("ldmatrix.sync.aligned.m8n8.x4.shared.b16 {%0,%1,%2,%3}, [%4];"
                 : "=r"(r[0]), "=r"(r[1]), "=r"(r[2]), "=r"(r[3]) : "r"(addr));
}
__device__ __forceinline__ void mma16816(float* d, const uint32_t* a, uint32_t b0, uint32_t b1) {
    asm volatile(
        "mma.sync.aligned.m16n8k16.row.col.f32.bf16.bf16.f32 "
        "{%0,%1,%2,%3}, {%4,%5,%6,%7}, {%8,%9}, {%0,%1,%2,%3};"
        : "+f"(d[0]), "+f"(d[1]), "+f"(d[2]), "+f"(d[3])
        : "r"(a[0]), "r"(a[1]), "r"(a[2]), "r"(a[3]), "r"(b0), "r"(b1));
}
#define STS8(addr, a, b) \
    asm volatile("st.shared.v2.b32 [%0], {%1, %2};" :: "r"(addr), "r"(a), "r"(b) : "memory")

// hi/lo bf16 split: 2 floats -> packed hi pair + lo pair
__device__ __forceinline__ void split2(float x, float y, uint32_t& h, uint32_t& l) {
    __nv_bfloat162 hb = __floats2bfloat162_rn(x, y);
    float2 hf = __bfloat1622float2(hb);
    __nv_bfloat162 lb = __floats2bfloat162_rn(x - hf.x, y - hf.y);
    h = *reinterpret_cast<uint32_t*>(&hb);
    l = *reinterpret_cast<uint32_t*>(&lb);
}
__device__ __forceinline__ uint32_t pack_bf16(float x, float y) {
    __nv_bfloat162 hb = __floats2bfloat162_rn(x, y);
    return *reinterpret_cast<uint32_t*>(&hb);
}

// ---------------------------------------------------------------- small kernels
__global__ void zero_kernel() { g_s = 0.0; g_ss = 0.0; }

__global__ void sumsq_kernel(const float* __restrict__ X) {
    __shared__ float sdata[NTH];
    float acc = 0.f;
    size_t n = (size_t)P * P;
    for (size_t i = (size_t)blockIdx.x * blockDim.x + threadIdx.x; i < n;
         i += (size_t)gridDim.x * blockDim.x) { float v = X[i]; acc += v * v; }
    sdata[threadIdx.x] = acc; __syncthreads();
    for (int s = NTH / 2; s > 0; s >>= 1) {
        if (threadIdx.x < s) sdata[threadIdx.x] += sdata[threadIdx.x + s];
        __syncthreads();
    }
    if (threadIdx.x == 0) atomicAdd(&g_s, (double)sdata[0]);
}

__global__ void rowsum_kernel(const float* __restrict__ Wb) {
    __shared__ float sdata[NTH];
    const float* rp = Wb + (size_t)blockIdx.x * P;
    float acc = 0.f;
    for (int j = threadIdx.x; j < P; j += NTH) acc += rp[j];
    sdata[threadIdx.x] = acc; __syncthreads();
    for (int s = NTH / 2; s > 0; s >>= 1) {
        if (threadIdx.x < s) sdata[threadIdx.x] += sdata[threadIdx.x + s];
        __syncthreads();
    }
    if (threadIdx.x == 0) g_W[blockIdx.x] = sdata[0];
}

__global__ void scale_kernel() {
    int i = blockIdx.x * blockDim.x + threadIdx.x;
    if (i < P) {
        float w = g_W[i], w2 = w * w;
        g_scale[i] = w2 / ((float)g_s * w2 + 1.0f);
    }
}

__global__ void transpose_kernel(const float* __restrict__ in, float* __restrict__ out) {
    __shared__ float tile[32][33];
    int x = blockIdx.x * 32 + threadIdx.x;
    int y0 = blockIdx.y * 32;
    for (int j = threadIdx.y; j < 32; j += 8)
        tile[j][threadIdx.x] = in[(size_t)(y0 + j) * P + x];
    __syncthreads();
    int x2 = blockIdx.y * 32 + threadIdx.x;
    int y2 = blockIdx.x * 32;
    for (int j = threadIdx.y; j < 32; j += 8)
        out[(size_t)(y2 + j) * P + x2] = tile[threadIdx.x][j];
}

__global__ void final_kernel(float* __restrict__ out) { out[0] = (float)sqrt(g_ss); }

// ---------------------------------------------------------------- HMMA GEMM
// D[m,n] = sum_k A[m,k]*B[n,k]; A,B f32 row-major (K contiguous).
// SPLIT: 2-term bf16 split of both operands, 3 MMA passes (hh, lh, hl).
// EPI 0: Cg = g_scale[row] * acc   EPI 1: Cg = acc - Dg   EPI 2: g_ss += acc^2
template <int EPI, bool SPLIT>
__global__ void __launch_bounds__(NTH, 1)
gemm_hmma(const float* __restrict__ Ag, const float* __restrict__ Bg,
          const float* __restrict__ Dg, float* __restrict__ Cg) {
    extern __shared__ char smem[];
    const uint32_t su = smem_to_u32(smem);
    const int tid = threadIdx.x;
    const int lane = tid & 31;
    const int wid = tid >> 5;
    const int rowBase = blockIdx.y * BM;
    const int colBase = blockIdx.x * BN;
    const int m64 = (wid & 1) * 64;     // warp M offset
    const int n32 = (wid >> 1) * 32;    // warp N offset

    // stage layout: [Ah, (Al), Bh, (Bl)] x 2 stages
    const uint32_t opb   = TILE_B;                       // 10240
    const uint32_t stage = SPLIT ? 4 * opb : 2 * opb;
    const uint32_t bOffH = SPLIT ? 2 * opb : opb;

    float acc[4][4][4];
#pragma unroll
    for (int i = 0; i < 4; i++)
#pragma unroll
        for (int j = 0; j < 4; j++)
#pragma unroll
            for (int q = 0; q < 4; q++) acc[i][j][q] = 0.f;

    // loader mapping: idx = tid + i*256; row = idx>>3 (0..127), q = idx&7 (float4 col)
    float4 aReg[4], bReg[4];
    {
        const int k0 = 0;
#pragma unroll
        for (int i = 0; i < 4; i++) {
            int idx = tid + i * NTH, row = idx >> 3, q = idx & 7;
            aReg[i] = *(const float4*)(Ag + (size_t)(rowBase + row) * P + k0 + q * 4);
            bReg[i] = *(const float4*)(Bg + (size_t)(colBase + row) * P + k0 + q * 4);
        }
    }

    // ldmatrix lane addressing (byte offsets within a tile, row stride 80B)
    const int aRowOff = (lane & 7) + ((lane >> 3) & 1) * 8;   // + m-tile base
    const int aCbOff  = (lane >> 4) * 16;                     // + ks*32
    const int bRowOff = (lane & 7) + ((lane >> 4) & 1) * 8;   // + n-pair base
    const int bCbOff  = ((lane >> 3) & 1) * 16;               // + ks*32

#pragma unroll 1
    for (int c = 0; c < NCH; c++) {
        const uint32_t sb = su + (c & 1) * stage;
        const uint32_t aH = sb, aL = sb + opb;
        const uint32_t bH = sb + bOffH, bL = bH + opb;

        // STS: convert f32 -> bf16 (hi[/lo]) into stage
#pragma unroll
        for (int i = 0; i < 4; i++) {
            int idx = tid + i * NTH, row = idx >> 3, q = idx & 7;
            uint32_t off = row * (LDT * 2) + q * 8;
            if (SPLIT) {
                uint32_t h0, l0, h1, l1;
                split2(aReg[i].x, aReg[i].y, h0, l0);
                split2(aReg[i].z, aReg[i].w, h1, l1);
                STS8(aH + off, h0, h1);
                STS8(aL + off, l0, l1);
                split2(bReg[i].x, bReg[i].y, h0, l0);
                split2(bReg[i].z, bReg[i].w, h1, l1);
                STS8(bH + off, h0, h1);
                STS8(bL + off, l0, l1);
            } else {
                STS8(aH + off, pack_bf16(aReg[i].x, aReg[i].y), pack_bf16(aReg[i].z, aReg[i].w));
                STS8(bH + off, pack_bf16(bReg[i].x, bReg[i].y), pack_bf16(bReg[i].z, bReg[i].w));
            }
        }
        __syncthreads();

        // prefetch next chunk
        if (c + 1 < NCH) {
            const int k0 = (c + 1) * BKF;
#pragma unroll
            for (int i = 0; i < 4; i++) {
                int idx = tid + i * NTH, row = idx >> 3, q = idx & 7;
                aReg[i] = *(const float4*)(Ag + (size_t)(rowBase + row) * P + k0 + q * 4);
                bReg[i] = *(const float4*)(Bg + (size_t)(colBase + row) * P + k0 + q * 4);
            }
        }

        // MMA passes over this stage
        const int npass = SPLIT ? 3 : 1;
#pragma unroll
        for (int pass = 0; pass < npass; pass++) {
            uint32_t aBase = (pass == 1) ? aL : aH;   // hh, lh, hl
            uint32_t bBase = (pass == 2) ? bL : bH;
#pragma unroll
            for (int ks = 0; ks < 2; ks++) {
                uint32_t af[4][4], bf[2][4];
#pragma unroll
                for (int mi = 0; mi < 4; mi++)
                    ldsm4(af[mi], aBase + (m64 + mi * 16 + aRowOff) * (LDT * 2) + ks * 32 + aCbOff);
#pragma unroll
                for (int np = 0; np < 2; np++)
                    ldsm4(bf[np], bBase + (n32 + np * 16 + bRowOff) * (LDT * 2) + ks * 32 + bCbOff);
#pragma unroll
                for (int mi = 0; mi < 4; mi++)
#pragma unroll
                    for (int np = 0; np < 2; np++) {
                        mma16816(acc[mi][np * 2 + 0], af[mi], bf[np][0], bf[np][1]);
                        mma16816(acc[mi][np * 2 + 1], af[mi], bf[np][2], bf[np][3]);
                    }
            }
        }
        __syncthreads();
    }

    // ---------------- epilogue ----------------
    const int rq = lane >> 2;            // row within 8
    const int cq = (lane & 3) * 2;       // col pair within 8
    float locss = 0.f;
#pragma unroll
    for (int mi = 0; mi < 4; mi++) {
        int r0 = rowBase + m64 + mi * 16 + rq;
        int r1 = r0 + 8;
        float s0 = 0.f, s1 = 0.f;
        if (EPI == 0) { s0 = g_scale[r0]; s1 = g_scale[r1]; }
#pragma unroll
        for (int ni = 0; ni < 4; ni++) {
            int cg = colBase + n32 + ni * 8 + cq;
            float* d = acc[mi][ni];
            if (EPI == 0) {
                *(float2*)(Cg + (size_t)r0 * P + cg) = make_float2(s0 * d[0], s0 * d[1]);
                *(float2*)(Cg + (size_t)r1 * P + cg) = make_float2(s1 * d[2], s1 * d[3]);
            } else if (EPI == 1) {
                float2 x0 = *(const float2*)(Dg + (size_t)r0 * P + cg);
                float2 x1 = *(const float2*)(Dg + (size_t)r1 * P + cg);
                *(float2*)(Cg + (size_t)r0 * P + cg) = make_float2(d[0] - x0.x, d[1] - x0.y);
                *(float2*)(Cg + (size_t)r1 * P + cg) = make_float2(d[2] - x1.x, d[3] - x1.y);
            } else {
                locss += d[0] * d[0] + d[1] * d[1] + d[2] * d[2] + d[3] * d[3];
            }
        }
    }
    if (EPI == 2) {
        __syncthreads();
        float* red = (float*)smem;
        red[tid] = locss;
        __syncthreads();
        for (int s = NTH / 2; s > 0; s >>= 1) {
            if (tid < s) red[tid] += red[tid + s];
            __syncthreads();
        }
        if (tid == 0) atomicAdd(&g_ss, (double)red[0]);
    }
}

// ---------------------------------------------------------------- launch
extern "C" void kernel_launch(void* const* d_in, const int* in_sizes, int n_in,
                              void* d_out, int out_size) {
    const float* target = (const float*)d_in[0];
    const float* source = (const float*)d_in[1];
    const float* Wbeta  = (const float*)d_in[2];
    float* out = (float*)d_out;   // out[0]=loss, out[1:]=W_matrix

    float *Wm, *tgtT, *srcT, *PT;
    cudaGetSymbolAddress((void**)&Wm, g_Wm);
    cudaGetSymbolAddress((void**)&tgtT, g_tgtT);
    cudaGetSymbolAddress((void**)&srcT, g_srcT);
    cudaGetSymbolAddress((void**)&PT, g_PT);

    const int smemSplit = 8 * TILE_B;   // 81920
    const int smemPlain = 4 * TILE_B;   // 40960
    cudaFuncSetAttribute(gemm_hmma<0, true>,  cudaFuncAttributeMaxDynamicSharedMemorySize, smemSplit);
    cudaFuncSetAttribute(gemm_hmma<1, false>, cudaFuncAttributeMaxDynamicSharedMemorySize, smemPlain);
    cudaFuncSetAttribute(gemm_hmma<2, false>, cudaFuncAttributeMaxDynamicSharedMemorySize, smemPlain);

    zero_kernel<<<1, 1>>>();
    sumsq_kernel<<<2048, NTH>>>(target);
    rowsum_kernel<<<P, NTH>>>(Wbeta);
    scale_kernel<<<P / NTH, NTH>>>();

    dim3 tgrid(P / 32, P / 32), tblk(32, 8);
    transpose_kernel<<<tgrid, tblk>>>(target, tgtT);
    transpose_kernel<<<tgrid, tblk>>>(source, srcT);

    dim3 grid(P / BN, P / BM);  // 32 x 32
    // GEMM1 (accurate, split): g_Wm[i,j] = scale[i] * sum_k source[i,k]*target[j,k]
    gemm_hmma<0, true><<<grid, NTH, smemSplit>>>(source, target, nullptr, Wm);
    cudaMemcpyAsync(out + 1, Wm, (size_t)P * P * sizeof(float),
                    cudaMemcpyDeviceToDevice);
    // GEMM2 (plain bf16; matmul term is ~2.6e-4 vs source ~1, error negligible):
    // g_PT[j,i] = sum_k tgtT[j,k]*Wm[i,k] - srcT[j,i]  (= primary^T)
    gemm_hmma<1, false><<<grid, NTH, smemPlain>>>(tgtT, Wm, srcT, PT);
    // GEMM3 (plain bf16; only feeds sum of squares): g_ss += sum((Wbeta @ primary)^2)
    gemm_hmma<2, false><<<grid, NTH, smemPlain>>>(Wbeta, PT, nullptr, nullptr);

    final_kernel<<<1, 1>>>(out);
}

// round 7
// speedup vs baseline: 4.6617x; 1.2677x over previous
#include <cuda_runtime.h>
#include <cuda_bf16.h>
#include <cstdint>
#include <math.h>

#define P 4096
#define NTH 256
#define BM 128
#define BN 128
#define BKF 32                  // K elems per chunk
#define NCH (P / BKF)           // 128
#define LDT 40                  // padded smem row (bf16 elems) = 80B
#define TILE_B (128 * LDT * 2)  // 10240 B per operand tile

// ---------------------------------------------------------------- scratch
__device__ __nv_bfloat16 g_sHi[(size_t)P * P];
__device__ __nv_bfloat16 g_sLo[(size_t)P * P];
__device__ __nv_bfloat16 g_tHi[(size_t)P * P];
__device__ __nv_bfloat16 g_tLo[(size_t)P * P];
__device__ __nv_bfloat16 g_Wb16[(size_t)P * P];
__device__ __nv_bfloat16 g_tgtT16[(size_t)P * P];
__device__ __nv_bfloat16 g_Wm16[(size_t)P * P];
__device__ __nv_bfloat16 g_PT16[(size_t)P * P];
__device__ float  g_srcT[(size_t)P * P];
__device__ float  g_W[P];
__device__ float  g_scale[P];
__device__ double g_s;
__device__ double g_ss;

// ---------------------------------------------------------------- helpers
__device__ __forceinline__ uint32_t smem_to_u32(const void* p) {
    uint32_t a;
    asm("{ .reg .u64 t; cvta.to.shared.u64 t, %1; cvt.u32.u64 %0, t; }" : "=r"(a) : "l"(p));
    return a;
}
__device__ __forceinline__ void ldsm4(uint32_t* r, uint32_t addr) {
    asm volatile("ldmatrix.sync.aligned.m8n8.x4.shared.b16 {%0,%1,%2,%3}, [%4];"
                 : "=r"(r[0]), "=r"(r[1]), "=r"(r[2]), "=r"(r[3]) : "r"(addr));
}
__device__ __forceinline__ void mma16816(float* d, const uint32_t* a, uint32_t b0, uint32_t b1) {
    asm volatile(
        "mma.sync.aligned.m16n8k16.row.col.f32.bf16.bf16.f32 "
        "{%0,%1,%2,%3}, {%4,%5,%6,%7}, {%8,%9}, {%0,%1,%2,%3};"
        : "+f"(d[0]), "+f"(d[1]), "+f"(d[2]), "+f"(d[3])
        : "r"(a[0]), "r"(a[1]), "r"(a[2]), "r"(a[3]), "r"(b0), "r"(b1));
}
#define CP_ASYNC16(dst, src) \
    asm volatile("cp.async.cg.shared.global [%0], [%1], 16;" :: "r"(dst), "l"(src) : "memory")
#define CP_COMMIT() asm volatile("cp.async.commit_group;" ::: "memory")

__device__ __forceinline__ void split2(float x, float y, uint32_t& h, uint32_t& l) {
    __nv_bfloat162 hb = __floats2bfloat162_rn(x, y);
    float2 hf = __bfloat1622float2(hb);
    __nv_bfloat162 lb = __floats2bfloat162_rn(x - hf.x, y - hf.y);
    h = *reinterpret_cast<uint32_t*>(&hb);
    l = *reinterpret_cast<uint32_t*>(&lb);
}
__device__ __forceinline__ uint32_t pack_bf16(float x, float y) {
    __nv_bfloat162 hb = __floats2bfloat162_rn(x, y);
    return *reinterpret_cast<uint32_t*>(&hb);
}

// ---------------------------------------------------------------- small kernels
__global__ void zero_kernel() { g_s = 0.0; g_ss = 0.0; }

__global__ void sumsq_kernel(const float* __restrict__ X) {
    __shared__ float sdata[NTH];
    float acc = 0.f;
    size_t n = (size_t)P * P;
    for (size_t i = (size_t)blockIdx.x * blockDim.x + threadIdx.x; i < n;
         i += (size_t)gridDim.x * blockDim.x) { float v = X[i]; acc += v * v; }
    sdata[threadIdx.x] = acc; __syncthreads();
    for (int s = NTH / 2; s > 0; s >>= 1) {
        if (threadIdx.x < s) sdata[threadIdx.x] += sdata[threadIdx.x + s];
        __syncthreads();
    }
    if (threadIdx.x == 0) atomicAdd(&g_s, (double)sdata[0]);
}

__global__ void rowsum_kernel(const float* __restrict__ Wb) {
    __shared__ float sdata[NTH];
    const float* rp = Wb + (size_t)blockIdx.x * P;
    float acc = 0.f;
    for (int j = threadIdx.x; j < P; j += NTH) acc += rp[j];
    sdata[threadIdx.x] = acc; __syncthreads();
    for (int s = NTH / 2; s > 0; s >>= 1) {
        if (threadIdx.x < s) sdata[threadIdx.x] += sdata[threadIdx.x + s];
        __syncthreads();
    }
    if (threadIdx.x == 0) g_W[blockIdx.x] = sdata[0];
}

__global__ void scale_kernel() {
    int i = blockIdx.x * blockDim.x + threadIdx.x;
    if (i < P) {
        float w = g_W[i], w2 = w * w;
        g_scale[i] = w2 / ((float)g_s * w2 + 1.0f);
    }
}

// f32 -> (hi, lo) bf16 arrays
__global__ void convert_split_kernel(const float* __restrict__ in,
                                     __nv_bfloat16* __restrict__ hi,
                                     __nv_bfloat16* __restrict__ lo) {
    size_t n4 = (size_t)P * P / 4;
    for (size_t i = (size_t)blockIdx.x * blockDim.x + threadIdx.x; i < n4;
         i += (size_t)gridDim.x * blockDim.x) {
        float4 v = ((const float4*)in)[i];
        uint32_t h0, l0, h1, l1;
        split2(v.x, v.y, h0, l0);
        split2(v.z, v.w, h1, l1);
        ((uint2*)hi)[i] = make_uint2(h0, h1);
        ((uint2*)lo)[i] = make_uint2(l0, l1);
    }
}

__global__ void convert_plain_kernel(const float* __restrict__ in,
                                     __nv_bfloat16* __restrict__ o16) {
    size_t n4 = (size_t)P * P / 4;
    for (size_t i = (size_t)blockIdx.x * blockDim.x + threadIdx.x; i < n4;
         i += (size_t)gridDim.x * blockDim.x) {
        float4 v = ((const float4*)in)[i];
        ((uint2*)o16)[i] = make_uint2(pack_bf16(v.x, v.y), pack_bf16(v.z, v.w));
    }
}

__global__ void transpose_f32_kernel(const float* __restrict__ in, float* __restrict__ out) {
    __shared__ float tile[32][33];
    int x = blockIdx.x * 32 + threadIdx.x;
    int y0 = blockIdx.y * 32;
    for (int j = threadIdx.y; j < 32; j += 8)
        tile[j][threadIdx.x] = in[(size_t)(y0 + j) * P + x];
    __syncthreads();
    int x2 = blockIdx.y * 32 + threadIdx.x;
    int y2 = blockIdx.x * 32;
    for (int j = threadIdx.y; j < 32; j += 8)
        out[(size_t)(y2 + j) * P + x2] = tile[threadIdx.x][j];
}

__global__ void transpose_bf16_kernel(const float* __restrict__ in,
                                      __nv_bfloat16* __restrict__ out) {
    __shared__ float tile[32][33];
    int x = blockIdx.x * 32 + threadIdx.x;
    int y0 = blockIdx.y * 32;
    for (int j = threadIdx.y; j < 32; j += 8)
        tile[j][threadIdx.x] = in[(size_t)(y0 + j) * P + x];
    __syncthreads();
    int x2 = blockIdx.y * 32 + threadIdx.x;
    int y2 = blockIdx.x * 32;
    for (int j = threadIdx.y; j < 32; j += 8)
        out[(size_t)(y2 + j) * P + x2] = __float2bfloat16(tile[threadIdx.x][j]);
}

__global__ void final_kernel(float* __restrict__ out) { out[0] = (float)sqrt(g_ss); }

// ---------------------------------------------------------------- HMMA GEMM
// D[m,n] = sum_k A[m,k]*B[n,k]; operands pre-converted bf16 row-major.
// SPLIT: hi/lo operands, 3 passes (hh, lh, hl).
// EPI 0: Cf32[r,c] = scale[r]*acc (scalar stores, 4B-aligned dst OK)
//        C16[r,c]  = bf16 of same
// EPI 1: C16[r,c]  = bf16(acc - Dg[r,c])
// EPI 2: g_ss += sum(acc^2)
template <int EPI, bool SPLIT, int NSTAGE, int MAXB>
__global__ void __launch_bounds__(NTH, MAXB)
gemm_hmma(const __nv_bfloat16* __restrict__ Ah_, const __nv_bfloat16* __restrict__ Al_,
          const __nv_bfloat16* __restrict__ Bh_, const __nv_bfloat16* __restrict__ Bl_,
          const float* __restrict__ Dg, float* __restrict__ Cf32,
          __nv_bfloat16* __restrict__ C16) {
    extern __shared__ char smem[];
    const uint32_t su = smem_to_u32(smem);
    const int tid = threadIdx.x;
    const int lane = tid & 31;
    const int wid = tid >> 5;
    const int rowBase = blockIdx.y * BM;
    const int colBase = blockIdx.x * BN;
    const int m64 = (wid & 1) * 64;
    const int n32 = (wid >> 1) * 32;
    const uint32_t STAGE_B = (SPLIT ? 4 : 2) * TILE_B;

    float acc[4][4][4];
#pragma unroll
    for (int i = 0; i < 4; i++)
#pragma unroll
        for (int j = 0; j < 4; j++)
#pragma unroll
            for (int q = 0; q < 4; q++) acc[i][j][q] = 0.f;

    // cp.async producer: 512 16B-transfers per tile; tiles [Ah,(Al),Bh,(Bl)]
    auto issue = [&](int chunk) {
        const uint32_t sb = su + (uint32_t)(chunk % NSTAGE) * STAGE_B;
        const int k0 = chunk * BKF;
        const int NT = SPLIT ? 8 : 4;
#pragma unroll
        for (int t = 0; t < NT; t++) {
            int idx = tid + t * NTH;
            int tile = idx >> 9;
            int within = idx & 511;
            int row = within >> 2, q = within & 3;
            const __nv_bfloat16* src;
            int gRow;
            if (SPLIT) {
                src = (tile == 0) ? Ah_ : (tile == 1) ? Al_ : (tile == 2) ? Bh_ : Bl_;
                gRow = (tile < 2 ? rowBase : colBase) + row;
            } else {
                src = (tile == 0) ? Ah_ : Bh_;
                gRow = (tile == 0 ? rowBase : colBase) + row;
            }
            uint32_t dst = sb + (uint32_t)tile * TILE_B + row * (LDT * 2) + q * 16;
            CP_ASYNC16(dst, src + (size_t)gRow * P + k0 + q * 8);
        }
    };

    // ldmatrix lane addressing (byte offsets, row stride 80B) — validated in R6
    const int aRowOff = (lane & 7) + ((lane >> 3) & 1) * 8;
    const int aCbOff  = (lane >> 4) * 16;
    const int bRowOff = (lane & 7) + ((lane >> 4) & 1) * 8;
    const int bCbOff  = ((lane >> 3) & 1) * 16;

#pragma unroll
    for (int s = 0; s < NSTAGE - 1; s++) { issue(s); CP_COMMIT(); }

#pragma unroll 1
    for (int c = 0; c < NCH; c++) {
        asm volatile("cp.async.wait_group %0;" :: "n"(NSTAGE - 2) : "memory");
        __syncthreads();
        if (c + NSTAGE - 1 < NCH) issue(c + NSTAGE - 1);
        CP_COMMIT();  // one commit per iteration (empty at tail keeps wait semantics)

        const uint32_t sb = su + (uint32_t)(c % NSTAGE) * STAGE_B;
        const uint32_t aH = sb, aL = sb + TILE_B;
        const uint32_t bH = sb + (SPLIT ? 2 : 1) * TILE_B, bL = bH + TILE_B;

        const int npass = SPLIT ? 3 : 1;
#pragma unroll
        for (int pass = 0; pass < npass; pass++) {
            uint32_t aBase = (pass == 1) ? aL : aH;  // hh, lh, hl
            uint32_t bBase = (pass == 2) ? bL : bH;
#pragma unroll
            for (int ks = 0; ks < 2; ks++) {
                uint32_t af[4][4], bf[2][4];
#pragma unroll
                for (int mi = 0; mi < 4; mi++)
                    ldsm4(af[mi], aBase + (m64 + mi * 16 + aRowOff) * (LDT * 2) + ks * 32 + aCbOff);
#pragma unroll
                for (int np = 0; np < 2; np++)
                    ldsm4(bf[np], bBase + (n32 + np * 16 + bRowOff) * (LDT * 2) + ks * 32 + bCbOff);
#pragma unroll
                for (int mi = 0; mi < 4; mi++)
#pragma unroll
                    for (int np = 0; np < 2; np++) {
                        mma16816(acc[mi][np * 2 + 0], af[mi], bf[np][0], bf[np][1]);
                        mma16816(acc[mi][np * 2 + 1], af[mi], bf[np][2], bf[np][3]);
                    }
            }
        }
        __syncthreads();
    }

    // ---------------- epilogue ----------------
    const int rq = lane >> 2;
    const int cq = (lane & 3) * 2;
    float locss = 0.f;
#pragma unroll
    for (int mi = 0; mi < 4; mi++) {
        int r0 = rowBase + m64 + mi * 16 + rq;
        int r1 = r0 + 8;
        float s0 = 0.f, s1 = 0.f;
        if (EPI == 0) { s0 = g_scale[r0]; s1 = g_scale[r1]; }
#pragma unroll
        for (int ni = 0; ni < 4; ni++) {
            int cg = colBase + n32 + ni * 8 + cq;
            float* d = acc[mi][ni];
            if (EPI == 0) {
                float v0 = s0 * d[0], v1 = s0 * d[1];
                float v2 = s1 * d[2], v3 = s1 * d[3];
                // scalar f32 stores into 4B-aligned (unvectorizable) output
                Cf32[(size_t)r0 * P + cg]     = v0;
                Cf32[(size_t)r0 * P + cg + 1] = v1;
                Cf32[(size_t)r1 * P + cg]     = v2;
                Cf32[(size_t)r1 * P + cg + 1] = v3;
                *(uint32_t*)(C16 + (size_t)r0 * P + cg) = pack_bf16(v0, v1);
                *(uint32_t*)(C16 + (size_t)r1 * P + cg) = pack_bf16(v2, v3);
            } else if (EPI == 1) {
                float2 x0 = *(const float2*)(Dg + (size_t)r0 * P + cg);
                float2 x1 = *(const float2*)(Dg + (size_t)r1 * P + cg);
                *(uint32_t*)(C16 + (size_t)r0 * P + cg) = pack_bf16(d[0] - x0.x, d[1] - x0.y);
                *(uint32_t*)(C16 + (size_t)r1 * P + cg) = pack_bf16(d[2] - x1.x, d[3] - x1.y);
            } else {
                locss += d[0] * d[0] + d[1] * d[1] + d[2] * d[2] + d[3] * d[3];
            }
        }
    }
    if (EPI == 2) {
        __syncthreads();
        float* red = (float*)smem;
        red[tid] = locss;
        __syncthreads();
        for (int s = NTH / 2; s > 0; s >>= 1) {
            if (tid < s) red[tid] += red[tid + s];
            __syncthreads();
        }
        if (tid == 0) atomicAdd(&g_ss, (double)red[0]);
    }
}

// ---------------------------------------------------------------- launch
extern "C" void kernel_launch(void* const* d_in, const int* in_sizes, int n_in,
                              void* d_out, int out_size) {
    const float* target = (const float*)d_in[0];
    const float* source = (const float*)d_in[1];
    const float* Wbeta  = (const float*)d_in[2];
    float* out = (float*)d_out;   // out[0]=loss, out[1:]=W_matrix

    __nv_bfloat16 *sHi, *sLo, *tHi, *tLo, *Wb16, *tgtT16, *Wm16, *PT16;
    float* srcT;
    cudaGetSymbolAddress((void**)&sHi, g_sHi);
    cudaGetSymbolAddress((void**)&sLo, g_sLo);
    cudaGetSymbolAddress((void**)&tHi, g_tHi);
    cudaGetSymbolAddress((void**)&tLo, g_tLo);
    cudaGetSymbolAddress((void**)&Wb16, g_Wb16);
    cudaGetSymbolAddress((void**)&tgtT16, g_tgtT16);
    cudaGetSymbolAddress((void**)&Wm16, g_Wm16);
    cudaGetSymbolAddress((void**)&PT16, g_PT16);
    cudaGetSymbolAddress((void**)&srcT, g_srcT);

    const int smemPlain = 4 * 2 * TILE_B;   // 81920
    const int smemSplit = 3 * 4 * TILE_B;   // 122880
    cudaFuncSetAttribute((const void*)gemm_hmma<0, true, 3, 1>,
                         cudaFuncAttributeMaxDynamicSharedMemorySize, smemSplit);
    cudaFuncSetAttribute((const void*)gemm_hmma<1, false, 4, 2>,
                         cudaFuncAttributeMaxDynamicSharedMemorySize, smemPlain);
    cudaFuncSetAttribute((const void*)gemm_hmma<2, false, 4, 2>,
                         cudaFuncAttributeMaxDynamicSharedMemorySize, smemPlain);

    zero_kernel<<<1, 1>>>();
    sumsq_kernel<<<2048, NTH>>>(target);
    rowsum_kernel<<<P, NTH>>>(Wbeta);
    scale_kernel<<<P / NTH, NTH>>>();

    convert_split_kernel<<<1024, NTH>>>(source, sHi, sLo);
    convert_split_kernel<<<1024, NTH>>>(target, tHi, tLo);
    convert_plain_kernel<<<1024, NTH>>>(Wbeta, Wb16);
    dim3 tgrid(P / 32, P / 32), tblk(32, 8);
    transpose_bf16_kernel<<<tgrid, tblk>>>(target, tgtT16);
    transpose_f32_kernel<<<tgrid, tblk>>>(source, srcT);

    dim3 grid(P / BN, P / BM);  // 32 x 32
    // GEMM1 (split): out[1+i*P+j] = scale[i]*sum_k src[i,k]*tgt[j,k]; Wm16 same in bf16
    gemm_hmma<0, true, 3, 1><<<grid, NTH, smemSplit>>>(
        sHi, sLo, tHi, tLo, nullptr, out + 1, Wm16);
    // GEMM2 (plain): PT16[j,i] = bf16( sum_k tgtT[j,k]*Wm[i,k] - srcT[j,i] )
    gemm_hmma<1, false, 4, 2><<<grid, NTH, smemPlain>>>(
        tgtT16, nullptr, Wm16, nullptr, srcT, nullptr, PT16);
    // GEMM3 (plain): g_ss += sum( (sum_k Wb[i,k]*PT[j,k])^2 )
    gemm_hmma<2, false, 4, 2><<<grid, NTH, smemPlain>>>(
        Wb16, nullptr, PT16, nullptr, nullptr, nullptr, nullptr);

    final_kernel<<<1, 1>>>(out);
}

// round 8
// speedup vs baseline: 4.7997x; 1.0296x over previous
#include <cuda_runtime.h>
#include <cuda_bf16.h>
#include <cstdint>
#include <math.h>

#define P 4096
#define NTH 256
#define BM 128
#define BN 128
#define BKF 32                  // K elems per chunk
#define NCH (P / BKF)           // 128
#define LDT 40                  // padded smem row (bf16 elems) = 80B
#define TILE_B (128 * LDT * 2)  // 10240 B per operand tile

// ---------------------------------------------------------------- scratch
__device__ __nv_bfloat16 g_sHi[(size_t)P * P];
__device__ __nv_bfloat16 g_sLo[(size_t)P * P];
__device__ __nv_bfloat16 g_tHi[(size_t)P * P];
__device__ __nv_bfloat16 g_tLo[(size_t)P * P];
__device__ __nv_bfloat16 g_Wb16[(size_t)P * P];
__device__ __nv_bfloat16 g_tgtT16[(size_t)P * P];
__device__ __nv_bfloat16 g_Wm16[(size_t)P * P];
__device__ __nv_bfloat16 g_PT16[(size_t)P * P];
__device__ float  g_srcT[(size_t)P * P];
__device__ float  g_W[P];
__device__ float  g_scale[P];
__device__ double g_s;
__device__ double g_ss;

// ---------------------------------------------------------------- helpers
__device__ __forceinline__ uint32_t smem_to_u32(const void* p) {
    uint32_t a;
    asm("{ .reg .u64 t; cvta.to.shared.u64 t, %1; cvt.u32.u64 %0, t; }" : "=r"(a) : "l"(p));
    return a;
}
__device__ __forceinline__ void ldsm4(uint32_t* r, uint32_t addr) {
    asm volatile("ldmatrix.sync.aligned.m8n8.x4.shared.b16 {%0,%1,%2,%3}, [%4];"
                 : "=r"(r[0]), "=r"(r[1]), "=r"(r[2]), "=r"(r[3]) : "r"(addr));
}
__device__ __forceinline__ void mma16816(float* d, const uint32_t* a, uint32_t b0, uint32_t b1) {
    asm volatile(
        "mma.sync.aligned.m16n8k16.row.col.f32.bf16.bf16.f32 "
        "{%0,%1,%2,%3}, {%4,%5,%6,%7}, {%8,%9}, {%0,%1,%2,%3};"
        : "+f"(d[0]), "+f"(d[1]), "+f"(d[2]), "+f"(d[3])
        : "r"(a[0]), "r"(a[1]), "r"(a[2]), "r"(a[3]), "r"(b0), "r"(b1));
}
#define CP_ASYNC16(dst, src) \
    asm volatile("cp.async.cg.shared.global [%0], [%1], 16;" :: "r"(dst), "l"(src) : "memory")
#define CP_COMMIT() asm volatile("cp.async.commit_group;" ::: "memory")

__device__ __forceinline__ void split2(float x, float y, uint32_t& h, uint32_t& l) {
    __nv_bfloat162 hb = __floats2bfloat162_rn(x, y);
    float2 hf = __bfloat1622float2(hb);
    __nv_bfloat162 lb = __floats2bfloat162_rn(x - hf.x, y - hf.y);
    h = *reinterpret_cast<uint32_t*>(&hb);
    l = *reinterpret_cast<uint32_t*>(&lb);
}
__device__ __forceinline__ uint32_t pack_bf16(float x, float y) {
    __nv_bfloat162 hb = __floats2bfloat162_rn(x, y);
    return *reinterpret_cast<uint32_t*>(&hb);
}

// ---------------------------------------------------------------- small kernels
__global__ void zero_kernel() { g_s = 0.0; g_ss = 0.0; }

__global__ void sumsq_kernel(const float* __restrict__ X) {
    __shared__ float sdata[NTH];
    float acc = 0.f;
    size_t n = (size_t)P * P;
    for (size_t i = (size_t)blockIdx.x * blockDim.x + threadIdx.x; i < n;
         i += (size_t)gridDim.x * blockDim.x) { float v = X[i]; acc += v * v; }
    sdata[threadIdx.x] = acc; __syncthreads();
    for (int s = NTH / 2; s > 0; s >>= 1) {
        if (threadIdx.x < s) sdata[threadIdx.x] += sdata[threadIdx.x + s];
        __syncthreads();
    }
    if (threadIdx.x == 0) atomicAdd(&g_s, (double)sdata[0]);
}

__global__ void rowsum_kernel(const float* __restrict__ Wb) {
    __shared__ float sdata[NTH];
    const float* rp = Wb + (size_t)blockIdx.x * P;
    float acc = 0.f;
    for (int j = threadIdx.x; j < P; j += NTH) acc += rp[j];
    sdata[threadIdx.x] = acc; __syncthreads();
    for (int s = NTH / 2; s > 0; s >>= 1) {
        if (threadIdx.x < s) sdata[threadIdx.x] += sdata[threadIdx.x + s];
        __syncthreads();
    }
    if (threadIdx.x == 0) g_W[blockIdx.x] = sdata[0];
}

__global__ void scale_kernel() {
    int i = blockIdx.x * blockDim.x + threadIdx.x;
    if (i < P) {
        float w = g_W[i], w2 = w * w;
        g_scale[i] = w2 / ((float)g_s * w2 + 1.0f);
    }
}

__global__ void convert_split_kernel(const float* __restrict__ in,
                                     __nv_bfloat16* __restrict__ hi,
                                     __nv_bfloat16* __restrict__ lo) {
    size_t n4 = (size_t)P * P / 4;
    for (size_t i = (size_t)blockIdx.x * blockDim.x + threadIdx.x; i < n4;
         i += (size_t)gridDim.x * blockDim.x) {
        float4 v = ((const float4*)in)[i];
        uint32_t h0, l0, h1, l1;
        split2(v.x, v.y, h0, l0);
        split2(v.z, v.w, h1, l1);
        ((uint2*)hi)[i] = make_uint2(h0, h1);
        ((uint2*)lo)[i] = make_uint2(l0, l1);
    }
}

__global__ void convert_plain_kernel(const float* __restrict__ in,
                                     __nv_bfloat16* __restrict__ o16) {
    size_t n4 = (size_t)P * P / 4;
    for (size_t i = (size_t)blockIdx.x * blockDim.x + threadIdx.x; i < n4;
         i += (size_t)gridDim.x * blockDim.x) {
        float4 v = ((const float4*)in)[i];
        ((uint2*)o16)[i] = make_uint2(pack_bf16(v.x, v.y), pack_bf16(v.z, v.w));
    }
}

__global__ void transpose_f32_kernel(const float* __restrict__ in, float* __restrict__ out) {
    __shared__ float tile[32][33];
    int x = blockIdx.x * 32 + threadIdx.x;
    int y0 = blockIdx.y * 32;
    for (int j = threadIdx.y; j < 32; j += 8)
        tile[j][threadIdx.x] = in[(size_t)(y0 + j) * P + x];
    __syncthreads();
    int x2 = blockIdx.y * 32 + threadIdx.x;
    int y2 = blockIdx.x * 32;
    for (int j = threadIdx.y; j < 32; j += 8)
        out[(size_t)(y2 + j) * P + x2] = tile[threadIdx.x][j];
}

__global__ void transpose_bf16_kernel(const float* __restrict__ in,
                                      __nv_bfloat16* __restrict__ out) {
    __shared__ float tile[32][33];
    int x = blockIdx.x * 32 + threadIdx.x;
    int y0 = blockIdx.y * 32;
    for (int j = threadIdx.y; j < 32; j += 8)
        tile[j][threadIdx.x] = in[(size_t)(y0 + j) * P + x];
    __syncthreads();
    int x2 = blockIdx.y * 32 + threadIdx.x;
    int y2 = blockIdx.x * 32;
    for (int j = threadIdx.y; j < 32; j += 8)
        out[(size_t)(y2 + j) * P + x2] = __float2bfloat16(tile[threadIdx.x][j]);
}

__global__ void final_kernel(float* __restrict__ out) { out[0] = (float)sqrt(g_ss); }

// ---------------------------------------------------------------- HMMA GEMM
// D[m,n] = sum_k A[m,k]*B[n,k]; operands pre-converted bf16 row-major.
// SPLIT: hi/lo operands, 3 passes (hh, lh, hl).
// EPI 0: Cf32 = scale[r]*acc (scalar stores into 4B-aligned out), C16 = bf16(same)
// EPI 1: C16 = bf16(acc - Dg)
// EPI 2: g_ss += sum(acc^2)
template <int EPI, bool SPLIT, int NSTAGE>
__global__ void __launch_bounds__(NTH, 2)
gemm_hmma(const __nv_bfloat16* __restrict__ Ah_, const __nv_bfloat16* __restrict__ Al_,
          const __nv_bfloat16* __restrict__ Bh_, const __nv_bfloat16* __restrict__ Bl_,
          const float* __restrict__ Dg, float* __restrict__ Cf32,
          __nv_bfloat16* __restrict__ C16) {
    extern __shared__ char smem[];
    const uint32_t su = smem_to_u32(smem);
    const int tid = threadIdx.x;
    const int lane = tid & 31;
    const int wid = tid >> 5;
    const int rowBase = blockIdx.y * BM;
    const int colBase = blockIdx.x * BN;
    const int m64 = (wid & 1) * 64;
    const int n32 = (wid >> 1) * 32;
    const uint32_t STAGE_B = (SPLIT ? 4 : 2) * TILE_B;

    float acc[4][4][4];
#pragma unroll
    for (int i = 0; i < 4; i++)
#pragma unroll
        for (int j = 0; j < 4; j++)
#pragma unroll
            for (int q = 0; q < 4; q++) acc[i][j][q] = 0.f;

    // cp.async producer: 512 16B-transfers per tile; tiles [Ah,(Al),Bh,(Bl)]
    auto issue = [&](int chunk) {
        const uint32_t sb = su + (uint32_t)(chunk % NSTAGE) * STAGE_B;
        const int k0 = chunk * BKF;
        const int NT = SPLIT ? 8 : 4;
#pragma unroll
        for (int t = 0; t < NT; t++) {
            int idx = tid + t * NTH;
            int tile = idx >> 9;
            int within = idx & 511;
            int row = within >> 2, q = within & 3;
            const __nv_bfloat16* src;
            int gRow;
            if (SPLIT) {
                src = (tile == 0) ? Ah_ : (tile == 1) ? Al_ : (tile == 2) ? Bh_ : Bl_;
                gRow = (tile < 2 ? rowBase : colBase) + row;
            } else {
                src = (tile == 0) ? Ah_ : Bh_;
                gRow = (tile == 0 ? rowBase : colBase) + row;
            }
            uint32_t dst = sb + (uint32_t)tile * TILE_B + row * (LDT * 2) + q * 16;
            CP_ASYNC16(dst, src + (size_t)gRow * P + k0 + q * 8);
        }
    };

    // ldmatrix lane addressing (byte offsets, row stride 80B) — validated R6/R7
    const int aRowOff = (lane & 7) + ((lane >> 3) & 1) * 8;
    const int aCbOff  = (lane >> 4) * 16;
    const int bRowOff = (lane & 7) + ((lane >> 4) & 1) * 8;
    const int bCbOff  = ((lane >> 3) & 1) * 16;

    // prologue: NSTAGE-1 chunks in flight
#pragma unroll
    for (int s = 0; s < NSTAGE - 1; s++) { issue(s); CP_COMMIT(); }

#pragma unroll 1
    for (int c = 0; c < NCH; c++) {
        // issue-ahead THEN wait: newest group stays in flight while we wait
        // for chunk c. issue(c+NSTAGE-1) writes stage (c-1)%NSTAGE, whose
        // compute finished behind the trailing sync of iteration c-1.
        if (c + NSTAGE - 1 < NCH) issue(c + NSTAGE - 1);
        CP_COMMIT();  // empty at tail keeps group accounting
        asm volatile("cp.async.wait_group %0;" :: "n"(NSTAGE - 1) : "memory");
        __syncthreads();

        const uint32_t sb = su + (uint32_t)(c % NSTAGE) * STAGE_B;
        const uint32_t aH = sb, aL = sb + TILE_B;
        const uint32_t bH = sb + (SPLIT ? 2 : 1) * TILE_B, bL = bH + TILE_B;

        const int npass = SPLIT ? 3 : 1;
#pragma unroll
        for (int pass = 0; pass < npass; pass++) {
            uint32_t aBase = (pass == 1) ? aL : aH;  // hh, lh, hl
            uint32_t bBase = (pass == 2) ? bL : bH;
#pragma unroll
            for (int ks = 0; ks < 2; ks++) {
                uint32_t af[4][4], bf[2][4];
#pragma unroll
                for (int mi = 0; mi < 4; mi++)
                    ldsm4(af[mi], aBase + (m64 + mi * 16 + aRowOff) * (LDT * 2) + ks * 32 + aCbOff);
#pragma unroll
                for (int np = 0; np < 2; np++)
                    ldsm4(bf[np], bBase + (n32 + np * 16 + bRowOff) * (LDT * 2) + ks * 32 + bCbOff);
#pragma unroll
                for (int mi = 0; mi < 4; mi++)
#pragma unroll
                    for (int np = 0; np < 2; np++) {
                        mma16816(acc[mi][np * 2 + 0], af[mi], bf[np][0], bf[np][1]);
                        mma16816(acc[mi][np * 2 + 1], af[mi], bf[np][2], bf[np][3]);
                    }
            }
        }
        __syncthreads();
    }

    // ---------------- epilogue ----------------
    const int rq = lane >> 2;
    const int cq = (lane & 3) * 2;
    float locss = 0.f;
#pragma unroll
    for (int mi = 0; mi < 4; mi++) {
        int r0 = rowBase + m64 + mi * 16 + rq;
        int r1 = r0 + 8;
        float s0 = 0.f, s1 = 0.f;
        if (EPI == 0) { s0 = g_scale[r0]; s1 = g_scale[r1]; }
#pragma unroll
        for (int ni = 0; ni < 4; ni++) {
            int cg = colBase + n32 + ni * 8 + cq;
            float* d = acc[mi][ni];
            if (EPI == 0) {
                float v0 = s0 * d[0], v1 = s0 * d[1];
                float v2 = s1 * d[2], v3 = s1 * d[3];
                Cf32[(size_t)r0 * P + cg]     = v0;
                Cf32[(size_t)r0 * P + cg + 1] = v1;
                Cf32[(size_t)r1 * P + cg]     = v2;
                Cf32[(size_t)r1 * P + cg + 1] = v3;
                *(uint32_t*)(C16 + (size_t)r0 * P + cg) = pack_bf16(v0, v1);
                *(uint32_t*)(C16 + (size_t)r1 * P + cg) = pack_bf16(v2, v3);
            } else if (EPI == 1) {
                float2 x0 = *(const float2*)(Dg + (size_t)r0 * P + cg);
                float2 x1 = *(const float2*)(Dg + (size_t)r1 * P + cg);
                *(uint32_t*)(C16 + (size_t)r0 * P + cg) = pack_bf16(d[0] - x0.x, d[1] - x0.y);
                *(uint32_t*)(C16 + (size_t)r1 * P + cg) = pack_bf16(d[2] - x1.x, d[3] - x1.y);
            } else {
                locss += d[0] * d[0] + d[1] * d[1] + d[2] * d[2] + d[3] * d[3];
            }
        }
    }
    if (EPI == 2) {
        __syncthreads();
        float* red = (float*)smem;
        red[tid] = locss;
        __syncthreads();
        for (int s = NTH / 2; s > 0; s >>= 1) {
            if (tid < s) red[tid] += red[tid + s];
            __syncthreads();
        }
        if (tid == 0) atomicAdd(&g_ss, (double)red[0]);
    }
}

// ---------------------------------------------------------------- launch
extern "C" void kernel_launch(void* const* d_in, const int* in_sizes, int n_in,
                              void* d_out, int out_size) {
    const float* target = (const float*)d_in[0];
    const float* source = (const float*)d_in[1];
    const float* Wbeta  = (const float*)d_in[2];
    float* out = (float*)d_out;   // out[0]=loss, out[1:]=W_matrix

    __nv_bfloat16 *sHi, *sLo, *tHi, *tLo, *Wb16, *tgtT16, *Wm16, *PT16;
    float* srcT;
    cudaGetSymbolAddress((void**)&sHi, g_sHi);
    cudaGetSymbolAddress((void**)&sLo, g_sLo);
    cudaGetSymbolAddress((void**)&tHi, g_tHi);
    cudaGetSymbolAddress((void**)&tLo, g_tLo);
    cudaGetSymbolAddress((void**)&Wb16, g_Wb16);
    cudaGetSymbolAddress((void**)&tgtT16, g_tgtT16);
    cudaGetSymbolAddress((void**)&Wm16, g_Wm16);
    cudaGetSymbolAddress((void**)&PT16, g_PT16);
    cudaGetSymbolAddress((void**)&srcT, g_srcT);

    const int smemPlain = 4 * 2 * TILE_B;   // 81920 (4 stages x 2 tiles)
    const int smemSplit = 2 * 4 * TILE_B;   // 81920 (2 stages x 4 tiles) -> 2 CTAs/SM
    cudaFuncSetAttribute((const void*)gemm_hmma<0, true, 2>,
                         cudaFuncAttributeMaxDynamicSharedMemorySize, smemSplit);
    cudaFuncSetAttribute((const void*)gemm_hmma<1, false, 4>,
                         cudaFuncAttributeMaxDynamicSharedMemorySize, smemPlain);
    cudaFuncSetAttribute((const void*)gemm_hmma<2, false, 4>,
                         cudaFuncAttributeMaxDynamicSharedMemorySize, smemPlain);

    zero_kernel<<<1, 1>>>();
    sumsq_kernel<<<2048, NTH>>>(target);
    rowsum_kernel<<<P, NTH>>>(Wbeta);
    scale_kernel<<<P / NTH, NTH>>>();

    convert_split_kernel<<<1024, NTH>>>(source, sHi, sLo);
    convert_split_kernel<<<1024, NTH>>>(target, tHi, tLo);
    convert_plain_kernel<<<1024, NTH>>>(Wbeta, Wb16);
    dim3 tgrid(P / 32, P / 32), tblk(32, 8);
    transpose_bf16_kernel<<<tgrid, tblk>>>(target, tgtT16);
    transpose_f32_kernel<<<tgrid, tblk>>>(source, srcT);

    dim3 grid(P / BN, P / BM);  // 32 x 32
    // GEMM1 (split, 2 CTAs/SM): out[1+i*P+j] = scale[i]*sum_k src[i,k]*tgt[j,k]
    gemm_hmma<0, true, 2><<<grid, NTH, smemSplit>>>(
        sHi, sLo, tHi, tLo, nullptr, out + 1, Wm16);
    // GEMM2 (plain): PT16[j,i] = bf16( sum_k tgtT[j,k]*Wm[i,k] - srcT[j,i] )
    gemm_hmma<1, false, 4><<<grid, NTH, smemPlain>>>(
        tgtT16, nullptr, Wm16, nullptr, srcT, nullptr, PT16);
    // GEMM3 (plain): g_ss += sum( (sum_k Wb[i,k]*PT[j,k])^2 )
    gemm_hmma<2, false, 4><<<grid, NTH, smemPlain>>>(
        Wb16, nullptr, PT16, nullptr, nullptr, nullptr, nullptr);

    final_kernel<<<1, 1>>>(out);
}